// round 11
// baseline (speedup 1.0000x reference)
#include <cuda_runtime.h>

#define IMG_H 512
#define IMG_W 512

typedef unsigned long long u64;

__constant__ u64   c_k2[9];    // conv weights packed {k,k}
__constant__ float c_pw[22];   // [0]=a, [1]=b, [2..11]=g_j, [12..21]=d_j (padded)
__constant__ int   c_cnt;      // interior-unit count (even, 0..10)

__device__ u64   d_k2s[9];
__device__ float d_pws[22];
__device__ int   d_cnts;

__device__ __forceinline__ u64 pack2(float lo, float hi) {
    u64 r; asm("mov.b64 %0, {%1, %2};" : "=l"(r) : "f"(lo), "f"(hi)); return r;
}
__device__ __forceinline__ void unpack2(u64 v, float& lo, float& hi) {
    asm("mov.b64 {%0, %1}, %2;" : "=f"(lo), "=f"(hi) : "l"(v));
}
__device__ __forceinline__ u64 ffma2(u64 a, u64 b, u64 c) {
    u64 r; asm("fma.rn.f32x2 %0, %1, %2, %3;" : "=l"(r) : "l"(a), "l"(b), "l"(c)); return r;
}
__device__ __forceinline__ u64 fmul2(u64 a, u64 b) {
    u64 r; asm("mul.rn.f32x2 %0, %1, %2;" : "=l"(r) : "l"(a), "l"(b)); return r;
}

// Fold units whose ReLU knot lies outside g-domain [0,1] into the affine part.
// s(g) = a*g + b + sum_{j<cnt} d_j*|g - g_j|   (exact rewrite; g = exp(-(v-1)^2))
__global__ void prep_kernel(const float* __restrict__ k,
                            const float* __restrict__ w1,
                            const float* __restrict__ b1,
                            const float* __restrict__ w2) {
    if (threadIdx.x != 0 || blockIdx.x != 0) return;
    for (int i = 0; i < 9; ++i) d_k2s[i] = pack2(k[i], k[i]);
    float a = 0.0f, b = 0.0f;
    int cnt = 0;
    float gj[10], dj[10];
    for (int j = 0; j < 10; ++j) {
        float W1 = w1[j], B1 = b1[j], W2 = w2[j];
        a += 0.5f * W2 * W1;
        b += 0.5f * W2 * B1;
        bool always_on  = (B1 >= 0.0f) && (W1 + B1 >= 0.0f);
        bool always_off = (B1 <= 0.0f) && (W1 + B1 <= 0.0f);
        if (always_on) {            // |x| = x on [0,1]
            a += 0.5f * W2 * W1;
            b += 0.5f * W2 * B1;
        } else if (always_off) {    // |x| = -x on [0,1]
            a -= 0.5f * W2 * W1;
            b -= 0.5f * W2 * B1;
        } else {                    // knot inside (0,1): keep abs term
            gj[cnt] = -B1 / W1;
            dj[cnt] = 0.5f * W2 * fabsf(W1);
            cnt++;
        }
    }
    if (cnt & 1) { gj[cnt] = 0.0f; dj[cnt] = 0.0f; cnt++; }  // pad to even
    d_pws[0] = a; d_pws[1] = b;
    for (int j = 0; j < 10; ++j) {
        d_pws[2 + j]  = (j < cnt) ? gj[j] : 0.0f;
        d_pws[12 + j] = (j < cnt) ? dj[j] : 0.0f;
    }
    d_cnts = cnt;
}

#define L2E 1.4426950408889634f

template <int N>
__device__ __forceinline__ float act(float v) {
    // g = exp2(-L2E*(v-1)^2): q = (v*(-L2E) + 2L2E)*v - L2E  (2 fma)
    float q = fmaf(v, -L2E, 2.0f * L2E);
    q = fmaf(q, v, -L2E);
    float g; asm("ex2.approx.f32 %0, %1;" : "=f"(g) : "f"(q));
    float s = fmaf(c_pw[0], g, c_pw[1]);
#pragma unroll
    for (int j = 0; j < N; ++j)
        s = fmaf(c_pw[12 + j], fabsf(g - c_pw[2 + j]), s);   // |.| free modifier
    float e; float m = s * -L2E;
    asm("ex2.approx.f32 %0, %1;" : "=f"(e) : "f"(m));        // e = exp(-s)
    float r;
    asm("rcp.approx.f32 %0, %1;" : "=f"(r) : "f"(1.0f + e));
    return r - 0.5f;                                          // sigmoid(s) - 0.5
}

// Tile body: T rows x 2 cols per thread; each row held as 3 packed pairs
//   P0={l,x}  P1={x,y}  P2={y,r}   (x,y = this thread's float2; l,r = halo)
template <int T, int N>
__device__ __forceinline__ void run_tile(const float* __restrict__ img,
                                         float* __restrict__ oimg,
                                         int c0, int y0) {
    u64 win[3][3];

    auto load_row = [&](int y, u64* P) {
        if (y < 0 || y >= IMG_H) {
            P[0] = 0ull; P[1] = 0ull; P[2] = 0ull;
            return;
        }
        const float* p = img + y * IMG_W + c0;
        float2 v = *reinterpret_cast<const float2*>(p);
        float l = (c0 > 0)         ? __ldg(p - 1) : 0.0f;
        float r = (c0 + 2 < IMG_W) ? __ldg(p + 2) : 0.0f;
        P[0] = pack2(l,   v.x);
        P[1] = pack2(v.x, v.y);
        P[2] = pack2(v.y, r);
    };

    load_row(y0 - 1, win[0]);
    load_row(y0,     win[1]);

#pragma unroll
    for (int t = 0; t < T; ++t) {
        const int y = y0 + t;
        u64* rm = win[(t + 0) % 3];
        u64* rc = win[(t + 1) % 3];
        u64* rp = win[(t + 2) % 3];
        load_row(y + 1, rp);

        // conv for the pixel pair (c0, c0+1): 9 packed FFMA
        u64 v = fmul2(c_k2[0], rm[0]);
        v = ffma2(c_k2[1], rm[1], v);
        v = ffma2(c_k2[2], rm[2], v);
        v = ffma2(c_k2[3], rc[0], v);
        v = ffma2(c_k2[4], rc[1], v);
        v = ffma2(c_k2[5], rc[2], v);
        v = ffma2(c_k2[6], rp[0], v);
        v = ffma2(c_k2[7], rp[1], v);
        v = ffma2(c_k2[8], rp[2], v);

        float f0, f1, x0, x1;
        unpack2(v, f0, f1);
        unpack2(rc[1], x0, x1);       // residual centers = {x, y}

        float2 o;
        o.x = x0 + act<N>(f0);
        o.y = x1 + act<N>(f1);
        *reinterpret_cast<float2*>(oimg + y * IMG_W + c0) = o;
    }
}

template <int T>
__global__ __launch_bounds__(256, 7) void step_kernel(const float* __restrict__ in,
                                                      float* __restrict__ out) {
    const int tx = threadIdx.x;                        // 0..31
    const int c0 = blockIdx.x * 64 + tx * 2;           // warp spans 64 contiguous cols
    const int b  = blockIdx.z;
    const int y0 = (blockIdx.y * blockDim.y + threadIdx.y) * T;

    const float* img  = in  + (size_t)b * (IMG_H * IMG_W);
    float*       oimg = out + (size_t)b * (IMG_H * IMG_W);

    const int n = c_cnt;                               // uniform dispatch
    if      (n == 0)  run_tile<T, 0 >(img, oimg, c0, y0);
    else if (n == 2)  run_tile<T, 2 >(img, oimg, c0, y0);
    else if (n == 4)  run_tile<T, 4 >(img, oimg, c0, y0);
    else if (n == 6)  run_tile<T, 6 >(img, oimg, c0, y0);
    else if (n == 8)  run_tile<T, 8 >(img, oimg, c0, y0);
    else              run_tile<T, 10>(img, oimg, c0, y0);
}

extern "C" void kernel_launch(void* const* d_in, const int* in_sizes, int n_in,
                              void* d_out, int out_size) {
    const float* x  = (const float*)d_in[0];
    const float* k  = (const float*)d_in[1];
    const float* w1 = (const float*)d_in[2];
    const float* b1 = (const float*)d_in[3];
    const float* w2 = (const float*)d_in[4];
    float* out = (float*)d_out;

    const int npix  = in_sizes[0];
    const int B     = npix / (IMG_H * IMG_W);
    const int steps = out_size / npix - 1;

    // Build derived params on device, then stage into constant memory
    // (real device addresses via cudaGetSymbolAddress — not host shadows).
    prep_kernel<<<1, 32>>>(k, w1, b1, w2);
    void *pk2 = nullptr, *ppw = nullptr, *pcnt = nullptr;
    cudaGetSymbolAddress(&pk2,  d_k2s);
    cudaGetSymbolAddress(&ppw,  d_pws);
    cudaGetSymbolAddress(&pcnt, d_cnts);
    cudaMemcpyToSymbolAsync(c_k2,  pk2,  9 * sizeof(u64),    0, cudaMemcpyDeviceToDevice, 0);
    cudaMemcpyToSymbolAsync(c_pw,  ppw,  22 * sizeof(float), 0, cudaMemcpyDeviceToDevice, 0);
    cudaMemcpyToSymbolAsync(c_cnt, pcnt, sizeof(int),        0, cudaMemcpyDeviceToDevice, 0);

    // Slice 0 of the output is the initial state
    cudaMemcpyAsync(out, x, (size_t)npix * sizeof(float), cudaMemcpyDeviceToDevice, 0);

    constexpr int T = 8;
    dim3 blk(32, 8, 1);
    dim3 grd(IMG_W / 64, IMG_H / (8 * T), B);   // (8, 8, B) = 1024 CTAs, single wave @7/SM

    for (int s = 0; s < steps; ++s) {
        const float* src = out + (size_t)s       * npix;
        float*       dst = out + (size_t)(s + 1) * npix;
        step_kernel<T><<<grd, blk>>>(src, dst);
    }
}

// round 12
// speedup vs baseline: 1.1104x; 1.1104x over previous
#include <cuda_runtime.h>

#define IMG_H 512
#define IMG_W 512

typedef unsigned long long u64;

__constant__ u64   c_k2[9];    // conv weights packed {k,k}
__constant__ float c_pw[22];   // [0]=a, [1]=b, [2..11]=g_j, [12..21]=d_j (padded)
__constant__ int   c_cnt;      // interior-unit count (even, 0..10)

__device__ u64   d_k2s[9];
__device__ float d_pws[22];
__device__ int   d_cnts;

__device__ __forceinline__ u64 pack2(float lo, float hi) {
    u64 r; asm("mov.b64 %0, {%1, %2};" : "=l"(r) : "f"(lo), "f"(hi)); return r;
}
__device__ __forceinline__ void unpack2(u64 v, float& lo, float& hi) {
    asm("mov.b64 {%0, %1}, %2;" : "=f"(lo), "=f"(hi) : "l"(v));
}
__device__ __forceinline__ u64 ffma2(u64 a, u64 b, u64 c) {
    u64 r; asm("fma.rn.f32x2 %0, %1, %2, %3;" : "=l"(r) : "l"(a), "l"(b), "l"(c)); return r;
}
__device__ __forceinline__ u64 fmul2(u64 a, u64 b) {
    u64 r; asm("mul.rn.f32x2 %0, %1, %2;" : "=l"(r) : "l"(a), "l"(b)); return r;
}

// Fold units whose ReLU knot lies outside g-domain [0,1] into the affine part.
// s(g) = a*g + b + sum_{j<cnt} d_j*|g - g_j|   (exact rewrite; g = exp(-(v-1)^2))
__global__ void prep_kernel(const float* __restrict__ k,
                            const float* __restrict__ w1,
                            const float* __restrict__ b1,
                            const float* __restrict__ w2) {
    if (threadIdx.x != 0 || blockIdx.x != 0) return;
    for (int i = 0; i < 9; ++i) d_k2s[i] = pack2(k[i], k[i]);
    float a = 0.0f, b = 0.0f;
    int cnt = 0;
    float gj[10], dj[10];
    for (int j = 0; j < 10; ++j) {
        float W1 = w1[j], B1 = b1[j], W2 = w2[j];
        a += 0.5f * W2 * W1;
        b += 0.5f * W2 * B1;
        bool always_on  = (B1 >= 0.0f) && (W1 + B1 >= 0.0f);
        bool always_off = (B1 <= 0.0f) && (W1 + B1 <= 0.0f);
        if (always_on) {            // |x| = x on [0,1]
            a += 0.5f * W2 * W1;
            b += 0.5f * W2 * B1;
        } else if (always_off) {    // |x| = -x on [0,1]
            a -= 0.5f * W2 * W1;
            b -= 0.5f * W2 * B1;
        } else {                    // knot inside (0,1): keep abs term
            gj[cnt] = -B1 / W1;
            dj[cnt] = 0.5f * W2 * fabsf(W1);
            cnt++;
        }
    }
    if (cnt & 1) { gj[cnt] = 0.0f; dj[cnt] = 0.0f; cnt++; }  // pad to even
    d_pws[0] = a; d_pws[1] = b;
    for (int j = 0; j < 10; ++j) {
        d_pws[2 + j]  = (j < cnt) ? gj[j] : 0.0f;
        d_pws[12 + j] = (j < cnt) ? dj[j] : 0.0f;
    }
    d_cnts = cnt;
}

#define L2E 1.4426950408889634f

template <int N>
__device__ __forceinline__ float act(float v) {
    float q = fmaf(v, -L2E, 2.0f * L2E);
    q = fmaf(q, v, -L2E);                                     // -L2E*(v-1)^2
    float g; asm("ex2.approx.f32 %0, %1;" : "=f"(g) : "f"(q));
    float s = fmaf(c_pw[0], g, c_pw[1]);
#pragma unroll
    for (int j = 0; j < N; ++j)
        s = fmaf(c_pw[12 + j], fabsf(g - c_pw[2 + j]), s);
    float e; float m = s * -L2E;
    asm("ex2.approx.f32 %0, %1;" : "=f"(e) : "f"(m));         // exp(-s)
    float r;
    asm("rcp.approx.f32 %0, %1;" : "=f"(r) : "f"(1.0f + e));
    return r - 0.5f;                                          // sigmoid(s)-0.5
}

// Tile geometry: CTA covers 64 cols x 64 rows. blockDim=(32,8), 2 cols x 8 rows/thread.
// Smem stage: 66 rows x 72 cols (interior at col 4, halos at cols 3 and 68).
#define TILE_W   64
#define TILE_H   64
#define SROWS    66
#define SSTRIDE  72     // floats; 288B = 18*16 -> STS.128-aligned interior

template <int N>
__device__ __forceinline__ void run_tile(const float* __restrict__ img,
                                         float* __restrict__ oimg,
                                         float* __restrict__ sm,
                                         int cb, int y0) {
    const int tid = threadIdx.y * 32 + threadIdx.x;

    // ---- stage tile + halo into smem (bulk LDG.128, latency amortized) ----
    {
        // interior: 66 rows x 16 quads
        for (int i = tid; i < SROWS * (TILE_W / 4); i += 256) {
            int r = i >> 4, q = i & 15;
            int gy = y0 - 1 + r;
            float4 v = make_float4(0.f, 0.f, 0.f, 0.f);
            if (gy >= 0 && gy < IMG_H)
                v = *reinterpret_cast<const float4*>(img + gy * IMG_W + cb + q * 4);
            *reinterpret_cast<float4*>(sm + r * SSTRIDE + 4 + q * 4) = v;
        }
        // halo columns: 66 rows x 2 sides
        for (int i = tid; i < SROWS * 2; i += 256) {
            int r = i >> 1, side = i & 1;
            int gy = y0 - 1 + r;
            int gc = side ? (cb + TILE_W) : (cb - 1);
            float v = 0.0f;
            if (gy >= 0 && gy < IMG_H && gc >= 0 && gc < IMG_W)
                v = __ldg(img + gy * IMG_W + gc);
            sm[r * SSTRIDE + (side ? (4 + TILE_W) : 3)] = v;
        }
    }
    __syncthreads();

    // ---- compute from smem: 2 cols x 8 rows per thread, 3-row reg window ----
    const int tx = threadIdx.x;
    const int ty = threadIdx.y;
    const int colb = 4 + 2 * tx;            // smem col of this thread's pair
    const int rbase = ty * 8;               // smem row of (first output row - 1)

    u64 win[3][3];
    auto load_srow = [&](int r, u64* P) {   // r = smem row index
        const float* row = sm + r * SSTRIDE;
        float2 v = *reinterpret_cast<const float2*>(row + colb);
        float l = row[colb - 1];
        float rr = row[colb + 2];
        P[0] = pack2(l,   v.x);
        P[1] = pack2(v.x, v.y);
        P[2] = pack2(v.y, rr);
    };

    load_srow(rbase,     win[0]);
    load_srow(rbase + 1, win[1]);

    const int gc = cb + 2 * tx;
#pragma unroll
    for (int t = 0; t < 8; ++t) {
        u64* rm = win[(t + 0) % 3];
        u64* rc = win[(t + 1) % 3];
        u64* rp = win[(t + 2) % 3];
        load_srow(rbase + t + 2, rp);

        u64 v = fmul2(c_k2[0], rm[0]);
        v = ffma2(c_k2[1], rm[1], v);
        v = ffma2(c_k2[2], rm[2], v);
        v = ffma2(c_k2[3], rc[0], v);
        v = ffma2(c_k2[4], rc[1], v);
        v = ffma2(c_k2[5], rc[2], v);
        v = ffma2(c_k2[6], rp[0], v);
        v = ffma2(c_k2[7], rp[1], v);
        v = ffma2(c_k2[8], rp[2], v);

        float f0, f1, x0, x1;
        unpack2(v, f0, f1);
        unpack2(rc[1], x0, x1);

        float2 o;
        o.x = x0 + act<N>(f0);
        o.y = x1 + act<N>(f1);
        *reinterpret_cast<float2*>(oimg + (y0 + ty * 8 + t) * IMG_W + gc) = o;
    }
}

__global__ __launch_bounds__(256, 7) void step_kernel(const float* __restrict__ in,
                                                      float* __restrict__ out) {
    __shared__ float sm[SROWS * SSTRIDE];
    const int cb = blockIdx.x * TILE_W;
    const int y0 = blockIdx.y * TILE_H;
    const int b  = blockIdx.z;

    const float* img  = in  + (size_t)b * (IMG_H * IMG_W);
    float*       oimg = out + (size_t)b * (IMG_H * IMG_W);

    const int n = c_cnt;                               // uniform dispatch
    if      (n == 0)  run_tile<0 >(img, oimg, sm, cb, y0);
    else if (n == 2)  run_tile<2 >(img, oimg, sm, cb, y0);
    else if (n == 4)  run_tile<4 >(img, oimg, sm, cb, y0);
    else if (n == 6)  run_tile<6 >(img, oimg, sm, cb, y0);
    else if (n == 8)  run_tile<8 >(img, oimg, sm, cb, y0);
    else              run_tile<10>(img, oimg, sm, cb, y0);
}

extern "C" void kernel_launch(void* const* d_in, const int* in_sizes, int n_in,
                              void* d_out, int out_size) {
    const float* x  = (const float*)d_in[0];
    const float* k  = (const float*)d_in[1];
    const float* w1 = (const float*)d_in[2];
    const float* b1 = (const float*)d_in[3];
    const float* w2 = (const float*)d_in[4];
    float* out = (float*)d_out;

    const int npix  = in_sizes[0];
    const int B     = npix / (IMG_H * IMG_W);
    const int steps = out_size / npix - 1;

    // Build derived params on device, then stage into constant memory
    // (real device addresses via cudaGetSymbolAddress — not host shadows).
    prep_kernel<<<1, 32>>>(k, w1, b1, w2);
    void *pk2 = nullptr, *ppw = nullptr, *pcnt = nullptr;
    cudaGetSymbolAddress(&pk2,  d_k2s);
    cudaGetSymbolAddress(&ppw,  d_pws);
    cudaGetSymbolAddress(&pcnt, d_cnts);
    cudaMemcpyToSymbolAsync(c_k2,  pk2,  9 * sizeof(u64),    0, cudaMemcpyDeviceToDevice, 0);
    cudaMemcpyToSymbolAsync(c_pw,  ppw,  22 * sizeof(float), 0, cudaMemcpyDeviceToDevice, 0);
    cudaMemcpyToSymbolAsync(c_cnt, pcnt, sizeof(int),        0, cudaMemcpyDeviceToDevice, 0);

    // Slice 0 of the output is the initial state
    cudaMemcpyAsync(out, x, (size_t)npix * sizeof(float), cudaMemcpyDeviceToDevice, 0);

    dim3 blk(32, 8, 1);
    dim3 grd(IMG_W / TILE_W, IMG_H / TILE_H, B);   // (8, 8, B) = 1024 CTAs

    for (int s = 0; s < steps; ++s) {
        const float* src = out + (size_t)s       * npix;
        float*       dst = out + (size_t)(s + 1) * npix;
        step_kernel<<<grd, blk>>>(src, dst);
    }
}